// round 6
// baseline (speedup 1.0000x reference)
#include <cuda_runtime.h>
#include <cuda_fp16.h>

// B=256, T_MAX=D_MAX=256, TP=DP=257
#define NTHREADS 512
#define L_PAD    66049          // 257*257
#define EPS_C    1e-12f

// Shared layout (floats)
#define U_OFF    0              // u[260]
#define V_OFF    260            // v[260]
#define RMAX_OFF 520            // row max [260]
#define RHAS_OFF 780            // row-has-assignment flags [260]
#define SUP_OFF  1040           // per-warp sum(u) partials [16]
#define SVP_OFF  1056           // per-warp sum(v) partials [16]
#define K_OFF    1072
#define SMEM_FLOATS 58112       // 232448 B / 4
#define KCAP     (SMEM_FLOATS - K_OFF)   // 57040 fp32 slots
#define SMEM_BYTES (SMEM_FLOATS * 4)

// Deterministic 3-way product: bit-identical across all transport recomputes.
__device__ __forceinline__ float tmul3(float u, float k, float v) {
    return __fmul_rn(__fmul_rn(u, k), v);
}

__device__ __forceinline__ int floor_pow2(int x) { return 1 << (31 - __clz(x)); }

template<bool F32>
__device__ void run_ex(const float* __restrict__ aff, int nt, int nd,
                       float* __restrict__ oT, float* __restrict__ oA,
                       float* sm)
{
    const int tid  = threadIdx.x;
    const int lane = tid & 31;
    const int w    = tid >> 5;

    // Row pitch: odd multiple of 4 (fp32) / 8 (fp16) for bank decorrelation.
    int ndp;
    if (F32) { ndp = (nd + 3) & ~3; if (((ndp >> 2) & 1) == 0) ndp += 4; }
    else     { ndp = (nd + 7) & ~7; if (((ndp >> 3) & 1) == 0) ndp += 8; }

    // Split factors: sr lanes cooperate on one row, sc lanes on one column.
    int sr = floor_pow2(NTHREADS / nt); if (sr > 16) sr = 16;
    int sc = floor_pow2(NTHREADS / nd); if (sc > 16) sc = 16;
    const int shr = 31 - __clz(sr);
    const int shc = 31 - __clz(sc);

    float*  u_s    = sm + U_OFF;
    float*  v_s    = sm + V_OFF;
    float*  rmax_s = sm + RMAX_OFF;
    float*  rhas   = sm + RHAS_OFF;
    float*  sup    = sm + SUP_OFF;
    float*  svp    = sm + SVP_OFF;
    float*  Kf     = sm + K_OFF;
    __half* Kh     = (__half*)(sm + K_OFF);

    // ---- Pre-zero K region (padding must be exactly 0) ----
    const int kwords = F32 ? nt * ndp : (nt * ndp) >> 1;   // floats, multiple of 4
    for (int i = tid * 4; i < kwords; i += NTHREADS * 4)
        *(float4*)(Kf + i) = make_float4(0.f, 0.f, 0.f, 0.f);

    // init v0 = 1 on c<=nd; interior partial sum = nd
    for (int c = tid; c < 260; c += NTHREADS) v_s[c] = (c <= nd) ? 1.f : 0.f;
    if (tid < 16) svp[tid] = (tid == 0) ? (float)nd : 0.f;
    __syncthreads();

    // ---- Build K = exp(10*aff) on interior ----
    {
        const int cq0 = F32 ? 4 * lane : 8 * lane;
        const int cq1 = 4 * lane + 128;
        for (int r = w; r < nt; r += 16) {
            const float* arow = aff + (size_t)r * 256;
            if (F32) {
                float* krow = Kf + (size_t)r * ndp;
                if (cq0 < nd) {
                    float x[4];
                    #pragma unroll
                    for (int i = 0; i < 4; i++) { int c = cq0 + i; x[i] = (c < nd) ? __expf(10.0f * arow[c]) : 0.f; }
                    *(float4*)(krow + cq0) = make_float4(x[0], x[1], x[2], x[3]);
                }
                if (cq1 < nd) {
                    float x[4];
                    #pragma unroll
                    for (int i = 0; i < 4; i++) { int c = cq1 + i; x[i] = (c < nd) ? __expf(10.0f * arow[c]) : 0.f; }
                    *(float4*)(krow + cq1) = make_float4(x[0], x[1], x[2], x[3]);
                }
            } else {
                __half* krow = Kh + (size_t)r * ndp;
                if (cq0 < nd) {
                    __half h[8];
                    #pragma unroll
                    for (int i = 0; i < 8; i++) { int c = cq0 + i; h[i] = __float2half_rn((c < nd) ? __expf(10.0f * arow[c]) : 0.f); }
                    *(uint4*)(krow + cq0) = *(uint4*)h;
                }
            }
        }
    }
    __syncthreads();

    const float ndf = (float)nd, ntf = (float)nt;
    float u_top = 0.f;

    // Pass-1 identity: sr lanes per row
    const int  r1    = tid >> shr;
    const int  sub1  = tid & (sr - 1);
    const bool ract  = r1 < nt;
    const int  cstep = F32 ? 4 * sr : 8 * sr;
    const int  c0    = F32 ? 4 * sub1 : 8 * sub1;

    // Pass-2 identity: sc lanes per column
    const int  c2    = tid >> shc;
    const int  sub2  = tid & (sc - 1);
    const bool cact  = c2 < nd;
    const int  pstep = sc * ndp;

    // ================= 100 Sinkhorn iterations =================
    for (int it = 0; it < 100; ++it) {
        // ---- Pass 1: u_r = 1/((Kv)_r + v[nd] + eps), sr-way split ----
        float sumv = v_s[nd];
        #pragma unroll
        for (int k = 0; k < 16; k++) sumv += svp[k];
        u_top = ndf / (sumv + EPS_C);
        const float v_dum = v_s[nd];

        float dot = 0.f;
        if (ract) {
            float a0 = 0.f, a1 = 0.f, a2 = 0.f, a3 = 0.f;
            if (F32) {
                const float* krow = Kf + (size_t)r1 * ndp;
                #pragma unroll 4
                for (int c = c0; c < ndp; c += cstep) {
                    float4 kk = *(const float4*)(krow + c);
                    float4 vv = *(const float4*)(v_s + c);
                    a0 = fmaf(kk.x, vv.x, a0); a1 = fmaf(kk.y, vv.y, a1);
                    a2 = fmaf(kk.z, vv.z, a2); a3 = fmaf(kk.w, vv.w, a3);
                }
            } else {
                const __half* krow = Kh + (size_t)r1 * ndp;
                #pragma unroll 2
                for (int c = c0; c < ndp; c += cstep) {
                    uint4  raw = *(const uint4*)(krow + c);
                    float4 v0  = *(const float4*)(v_s + c);
                    float4 v1  = *(const float4*)(v_s + c + 4);
                    float2 f;
                    f = __half22float2(*(__half2*)&raw.x); a0 = fmaf(f.x, v0.x, a0); a1 = fmaf(f.y, v0.y, a1);
                    f = __half22float2(*(__half2*)&raw.y); a2 = fmaf(f.x, v0.z, a2); a3 = fmaf(f.y, v0.w, a3);
                    f = __half22float2(*(__half2*)&raw.z); a0 = fmaf(f.x, v1.x, a0); a1 = fmaf(f.y, v1.y, a1);
                    f = __half22float2(*(__half2*)&raw.w); a2 = fmaf(f.x, v1.z, a2); a3 = fmaf(f.y, v1.w, a3);
                }
            }
            dot = (a0 + a1) + (a2 + a3);
        }
        // combine the sr partials (adjacent lanes)
        for (int o = sr >> 1; o; o >>= 1) dot += __shfl_xor_sync(0xffffffffu, dot, o);

        float u_val = 0.f;
        if (ract) {
            u_val = 1.0f / (dot + v_dum + EPS_C);
            if (sub1 == 0) u_s[r1] = u_val;
        }
        if (tid == 0) u_s[nt] = u_top;
        float su = (ract && sub1 == 0) ? u_val : 0.f;
        #pragma unroll
        for (int o = 16; o > 0; o >>= 1) su += __shfl_xor_sync(0xffffffffu, su, o);
        if (lane == 0) sup[w] = su;
        __syncthreads();

        // ---- Pass 2: v_c = 1/((K^T u)_c + u_top + eps), sc-way split ----
        float sumu = u_top;
        #pragma unroll
        for (int k = 0; k < 16; k++) sumu += sup[k];
        const float v_dnew = ntf / (sumu + EPS_C);

        float z = 0.f;
        if (cact) {
            float z0 = 0.f, z1 = 0.f, z2 = 0.f, z3 = 0.f;
            int r = sub2;
            if (F32) {
                const float* p = Kf + c2 + (size_t)sub2 * ndp;
                for (; r + 3 * sc < nt; r += 4 * sc) {
                    z0 = fmaf(p[0],         u_s[r],          z0);
                    z1 = fmaf(p[pstep],     u_s[r + sc],     z1);
                    z2 = fmaf(p[2 * pstep], u_s[r + 2 * sc], z2);
                    z3 = fmaf(p[3 * pstep], u_s[r + 3 * sc], z3);
                    p += 4 * pstep;
                }
                for (; r < nt; r += sc) { z0 = fmaf(p[0], u_s[r], z0); p += pstep; }
            } else {
                const __half* p = Kh + c2 + (size_t)sub2 * ndp;
                for (; r + 3 * sc < nt; r += 4 * sc) {
                    z0 = fmaf(__half2float(p[0]),         u_s[r],          z0);
                    z1 = fmaf(__half2float(p[pstep]),     u_s[r + sc],     z1);
                    z2 = fmaf(__half2float(p[2 * pstep]), u_s[r + 2 * sc], z2);
                    z3 = fmaf(__half2float(p[3 * pstep]), u_s[r + 3 * sc], z3);
                    p += 4 * pstep;
                }
                for (; r < nt; r += sc) { z0 = fmaf(__half2float(p[0]), u_s[r], z0); p += pstep; }
            }
            z = (z0 + z1) + (z2 + z3);
        }
        for (int o = sc >> 1; o; o >>= 1) z += __shfl_xor_sync(0xffffffffu, z, o);

        float myv = 0.f;
        if (cact) {
            myv = 1.0f / (z + u_top + EPS_C);
            if (sub2 == 0) v_s[c2] = myv;
        }
        if (tid == 0) v_s[nd] = v_dnew;
        float sv = (cact && sub2 == 0) ? myv : 0.f;
        #pragma unroll
        for (int o = 16; o > 0; o >>= 1) sv += __shfl_xor_sync(0xffffffffu, sv, o);
        if (lane == 0) svp[w] = sv;
        __syncthreads();
    }

    // ================= Epilogue (runs once; ~2% of time) =================
    const float v_dF = v_s[nd];
    const float u_tF = u_s[nt];
    const int   nd1  = nd + 1;

    // E1: row max, sr-way split per row
    if (tid < 260) rhas[tid] = 0.f;
    float rmx = 0.f;
    if (ract) {
        const float u = u_s[r1];
        if (F32) {
            const float* krow = Kf + (size_t)r1 * ndp;
            #pragma unroll 4
            for (int c = c0; c < ndp; c += cstep) {
                float4 kk = *(const float4*)(krow + c);
                float4 vv = *(const float4*)(v_s + c);
                rmx = fmaxf(rmx, tmul3(u, kk.x, vv.x));
                rmx = fmaxf(rmx, tmul3(u, kk.y, vv.y));
                rmx = fmaxf(rmx, tmul3(u, kk.z, vv.z));
                rmx = fmaxf(rmx, tmul3(u, kk.w, vv.w));
            }
        } else {
            const __half* krow = Kh + (size_t)r1 * ndp;
            for (int c = c0; c < ndp; c += cstep) {
                #pragma unroll
                for (int i = 0; i < 8; i++) {
                    int cc = c + i;
                    if (cc < nd) rmx = fmaxf(rmx, tmul3(u, __half2float(krow[cc]), v_s[cc]));
                }
            }
        }
    }
    for (int o = sr >> 1; o; o >>= 1) rmx = fmaxf(rmx, __shfl_xor_sync(0xffffffffu, rmx, o));
    if (ract && sub1 == 0) rmax_s[r1] = rmx;
    __syncthreads();

    // E2: column pass — col max, then writes. sc-way split per column.
    float cmx = 0.f;
    if (cact) {
        const float vc = v_s[c2];
        if (F32) {
            const float* p = Kf + c2 + (size_t)sub2 * ndp;
            for (int r = sub2; r < nt; r += sc) { cmx = fmaxf(cmx, tmul3(u_s[r], p[0], vc)); p += pstep; }
        } else {
            const __half* p = Kh + c2 + (size_t)sub2 * ndp;
            for (int r = sub2; r < nt; r += sc) { cmx = fmaxf(cmx, tmul3(u_s[r], __half2float(p[0]), vc)); p += pstep; }
        }
    }
    for (int o = sc >> 1; o; o >>= 1) cmx = fmaxf(cmx, __shfl_xor_sync(0xffffffffu, cmx, o));

    float colhas = 0.f;
    if (cact) {
        const float vc = v_s[c2];
        if (F32) {
            const float* p = Kf + c2 + (size_t)sub2 * ndp;
            for (int r = sub2; r < nt; r += sc) {
                float t = tmul3(u_s[r], p[0], vc);
                bool  a = (t == rmax_s[r]) && (t == cmx);
                size_t idx = (size_t)r * nd1 + c2;
                oT[idx] = t; oA[idx] = a ? 1.f : 0.f;
                if (a) { colhas = 1.f; rhas[r] = 1.f; }   // benign races: all write 1
                p += pstep;
            }
        } else {
            const __half* p = Kh + c2 + (size_t)sub2 * ndp;
            for (int r = sub2; r < nt; r += sc) {
                float t = tmul3(u_s[r], __half2float(p[0]), vc);
                bool  a = (t == rmax_s[r]) && (t == cmx);
                size_t idx = (size_t)r * nd1 + c2;
                oT[idx] = t; oA[idx] = a ? 1.f : 0.f;
                if (a) { colhas = 1.f; rhas[r] = 1.f; }
                p += pstep;
            }
        }
    }
    for (int o = sc >> 1; o; o >>= 1) colhas = fmaxf(colhas, __shfl_xor_sync(0xffffffffu, colhas, o));
    if (cact && sub2 == 0) {                         // births row
        size_t bidx = (size_t)nt * nd1 + c2;
        oT[bidx] = __fmul_rn(u_tF, v_s[c2]);
        oA[bidx] = (colhas > 0.f) ? 0.f : 1.f;
    }
    __syncthreads();

    if (tid < nt) {                                  // deaths column
        size_t idx = (size_t)tid * nd1 + nd;
        oT[idx] = __fmul_rn(u_s[tid], v_dF);
        oA[idx] = (rhas[tid] > 0.f) ? 0.f : 1.f;
    }
    if (tid == 0) {                                  // corner
        size_t idx = (size_t)nt * nd1 + nd;
        oT[idx] = __fmul_rn(u_tF, v_dF);
        oA[idx] = 0.f;
    }
    const int length = (nt + 1) * nd1;               // zero pad tail
    for (int k = length + tid; k < L_PAD; k += NTHREADS) { oT[k] = 0.f; oA[k] = 0.f; }
}

__global__ void __launch_bounds__(NTHREADS, 1)
assoc_kernel(const float* __restrict__ aff, const int* __restrict__ ndet,
             const int* __restrict__ ntrk, float* __restrict__ outT,
             float* __restrict__ outA)
{
    extern __shared__ float sm[];
    const int b  = blockIdx.x;
    const int nd = ndet[b];
    const int nt = ntrk[b];
    const float* affb = aff + (size_t)b * (256 * 256);
    float* oT = outT + (size_t)b * L_PAD;
    float* oA = outA + (size_t)b * L_PAD;

    int ndp4 = (nd + 3) & ~3;
    if (((ndp4 >> 2) & 1) == 0) ndp4 += 4;
    if (nt * ndp4 <= KCAP) run_ex<true >(affb, nt, nd, oT, oA, sm);
    else                   run_ex<false>(affb, nt, nd, oT, oA, sm);
}

extern "C" void kernel_launch(void* const* d_in, const int* in_sizes, int n_in,
                              void* d_out, int out_size)
{
    const float* aff  = (const float*)d_in[0];
    const int*   ndet = (const int*)d_in[1];
    const int*   ntrk = (const int*)d_in[2];
    const int    Bn   = in_sizes[1];

    float* out  = (float*)d_out;
    float* outA = out + (size_t)(out_size / 2);   // [t_flat | a_flat]

    cudaFuncSetAttribute(assoc_kernel, cudaFuncAttributeMaxDynamicSharedMemorySize, SMEM_BYTES);
    assoc_kernel<<<Bn, NTHREADS, SMEM_BYTES>>>(aff, ndet, ntrk, out, outA);
}

// round 7
// speedup vs baseline: 1.8666x; 1.8666x over previous
#include <cuda_runtime.h>
#include <cuda_fp16.h>

// B=256, T_MAX=D_MAX=256, TP=DP=257
#define NTHREADS 512
#define L_PAD    66049          // 257*257
#define EPS_C    1e-12f

// Shared layout (floats)
#define U_OFF    0              // u[260]
#define V_OFF    260            // v[260]
#define RMAX_OFF 520            // row max [260]   (also reused as cost[] during remap)
#define RHAS_OFF 780            // row-has-assignment flags [260] (reused as rank scratch)
#define SUP_OFF  1040           // per-warp sum(u) partials [16]
#define SVP_OFF  1056           // per-warp sum(v) partials [16]
#define PICK_OFF 1072           // chosen example index [1]
#define K_OFF    1076
#define SMEM_FLOATS 58112       // 232448 B / 4
#define KCAP     (SMEM_FLOATS - K_OFF)   // 57036 fp32 slots
#define SMEM_BYTES (SMEM_FLOATS * 4)

// Deterministic 3-way product: bit-identical across all transport recomputes.
__device__ __forceinline__ float tmul3(float u, float k, float v) {
    return __fmul_rn(__fmul_rn(u, k), v);
}

template<bool F32>
__device__ void run_ex(const float* __restrict__ aff, int nt, int nd,
                       float* __restrict__ oT, float* __restrict__ oA,
                       float* sm)
{
    const int tid  = threadIdx.x;
    const int lane = tid & 31;
    const int w    = tid >> 5;

    // Row pitch: odd multiple of 4 (fp32) / 8 (fp16) -> conflict-free
    // strided row loads in pass 1.
    int ndp;
    if (F32) { ndp = (nd + 3) & ~3; if (((ndp >> 2) & 1) == 0) ndp += 4; }
    else     { ndp = (nd + 7) & ~7; if (((ndp >> 3) & 1) == 0) ndp += 8; }

    float*  u_s    = sm + U_OFF;
    float*  v_s    = sm + V_OFF;
    float*  rmax_s = sm + RMAX_OFF;
    float*  rhas   = sm + RHAS_OFF;
    float*  sup    = sm + SUP_OFF;
    float*  svp    = sm + SVP_OFF;
    float*  Kf     = sm + K_OFF;
    __half* Kh     = (__half*)(sm + K_OFF);

    // ---- Pre-zero K region (padding must be exactly 0, never garbage) ----
    const int kwords = F32 ? nt * ndp : (nt * ndp) >> 1;   // floats, mult of 4
    for (int i = tid * 4; i < kwords; i += NTHREADS * 4)
        *(float4*)(Kf + i) = make_float4(0.f, 0.f, 0.f, 0.f);

    // init v0 = 1 on c<=nd; interior partial sum = nd
    for (int c = tid; c < 260; c += NTHREADS) v_s[c] = (c <= nd) ? 1.f : 0.f;
    if (tid < 16) svp[tid] = (tid == 0) ? (float)nd : 0.f;
    __syncthreads();

    // ---- Build K = exp(10*aff) on interior ----
    {
        const int cq0 = F32 ? 4 * lane : 8 * lane;
        const int cq1 = 4 * lane + 128;
        for (int r = w; r < nt; r += 16) {
            const float* arow = aff + (size_t)r * 256;
            if (F32) {
                float* krow = Kf + (size_t)r * ndp;
                if (cq0 < nd) {
                    float x[4];
                    #pragma unroll
                    for (int i = 0; i < 4; i++) { int c = cq0 + i; x[i] = (c < nd) ? __expf(10.0f * arow[c]) : 0.f; }
                    *(float4*)(krow + cq0) = make_float4(x[0], x[1], x[2], x[3]);
                }
                if (cq1 < nd) {
                    float x[4];
                    #pragma unroll
                    for (int i = 0; i < 4; i++) { int c = cq1 + i; x[i] = (c < nd) ? __expf(10.0f * arow[c]) : 0.f; }
                    *(float4*)(krow + cq1) = make_float4(x[0], x[1], x[2], x[3]);
                }
            } else {
                __half* krow = Kh + (size_t)r * ndp;
                if (cq0 < nd) {
                    __half h[8];
                    #pragma unroll
                    for (int i = 0; i < 8; i++) { int c = cq0 + i; h[i] = __float2half_rn((c < nd) ? __expf(10.0f * arow[c]) : 0.f); }
                    *(uint4*)(krow + cq0) = *(uint4*)h;
                }
            }
        }
    }
    __syncthreads();

    const float ndf = (float)nd, ntf = (float)nt;
    const int   nt4 = nt & ~3;
    const int   ndp2 = 2 * ndp, ndp3 = 3 * ndp, ndp4s = 4 * ndp;
    float u_top = 0.f;

    // ================= 100 Sinkhorn iterations, shuffle-free =================
    for (int it = 0; it < 100; ++it) {
        // ---- Pass 1: thread t = row t. u = 1/((Kv)_r + v[nd] + eps) ----
        float sumv = v_s[nd];
        #pragma unroll
        for (int k = 0; k < 16; k++) sumv += svp[k];
        u_top = ndf / (sumv + EPS_C);
        const float v_dum = v_s[nd];

        float u_val = 0.f;
        if (tid < nt) {
            float a0 = 0.f, a1 = 0.f, a2 = 0.f, a3 = 0.f;
            if (F32) {
                const float* krow = Kf + (size_t)tid * ndp;
                #pragma unroll 4
                for (int c = 0; c < ndp; c += 4) {
                    float4 kk = *(const float4*)(krow + c);
                    float4 vv = *(const float4*)(v_s + c);     // warp-uniform broadcast
                    a0 = fmaf(kk.x, vv.x, a0); a1 = fmaf(kk.y, vv.y, a1);
                    a2 = fmaf(kk.z, vv.z, a2); a3 = fmaf(kk.w, vv.w, a3);
                }
            } else {
                const __half* krow = Kh + (size_t)tid * ndp;
                #pragma unroll 2
                for (int c = 0; c < ndp; c += 8) {
                    uint4  raw = *(const uint4*)(krow + c);
                    float4 v0  = *(const float4*)(v_s + c);
                    float4 v1  = *(const float4*)(v_s + c + 4);
                    float2 f;
                    f = __half22float2(*(__half2*)&raw.x); a0 = fmaf(f.x, v0.x, a0); a1 = fmaf(f.y, v0.y, a1);
                    f = __half22float2(*(__half2*)&raw.y); a2 = fmaf(f.x, v0.z, a2); a3 = fmaf(f.y, v0.w, a3);
                    f = __half22float2(*(__half2*)&raw.z); a0 = fmaf(f.x, v1.x, a0); a1 = fmaf(f.y, v1.y, a1);
                    f = __half22float2(*(__half2*)&raw.w); a2 = fmaf(f.x, v1.z, a2); a3 = fmaf(f.y, v1.w, a3);
                }
            }
            float dot = (a0 + a1) + (a2 + a3);
            u_val = 1.0f / (dot + v_dum + EPS_C);
            u_s[tid] = u_val;
        }
        if (tid == 0) u_s[nt] = u_top;
        // one small butterfly per warp for sum(u) (interior only)
        float su = u_val;
        #pragma unroll
        for (int o = 16; o > 0; o >>= 1) su += __shfl_xor_sync(0xffffffffu, su, o);
        if (lane == 0) sup[w] = su;
        __syncthreads();

        // ---- Pass 2: thread t = col t. v = 1/((K^T u)_c + u_top + eps) ----
        float sumu = u_top;
        #pragma unroll
        for (int k = 0; k < 16; k++) sumu += sup[k];
        const float v_dnew = ntf / (sumu + EPS_C);

        float myv = 0.f;
        if (tid < nd) {
            float z0 = 0.f, z1 = 0.f, z2 = 0.f, z3 = 0.f;
            int r = 0;
            if (F32) {
                const float* p = Kf + tid;                     // coalesced column reads
                for (; r < nt4; r += 4) {
                    float4 uu = *(const float4*)(u_s + r);     // broadcast
                    z0 = fmaf(p[0],     uu.x, z0);
                    z1 = fmaf(p[ndp],   uu.y, z1);
                    z2 = fmaf(p[ndp2],  uu.z, z2);
                    z3 = fmaf(p[ndp3],  uu.w, z3);
                    p += ndp4s;
                }
                for (; r < nt; r++) z0 = fmaf(Kf[tid + (size_t)r * ndp], u_s[r], z0);
            } else {
                const __half* p = Kh + tid;
                for (; r < nt4; r += 4) {
                    float4 uu = *(const float4*)(u_s + r);
                    z0 = fmaf(__half2float(p[0]),    uu.x, z0);
                    z1 = fmaf(__half2float(p[ndp]),  uu.y, z1);
                    z2 = fmaf(__half2float(p[ndp2]), uu.z, z2);
                    z3 = fmaf(__half2float(p[ndp3]), uu.w, z3);
                    p += ndp4s;
                }
                for (; r < nt; r++) z0 = fmaf(__half2float(Kh[tid + (size_t)r * ndp]), u_s[r], z0);
            }
            float z = ((z0 + z1) + (z2 + z3)) + u_top;
            myv = 1.0f / (z + EPS_C);
            v_s[tid] = myv;
        }
        if (tid == 0) v_s[nd] = v_dnew;
        float sv = myv;
        #pragma unroll
        for (int o = 16; o > 0; o >>= 1) sv += __shfl_xor_sync(0xffffffffu, sv, o);
        if (lane == 0) svp[w] = sv;
        __syncthreads();
    }

    // ================= Epilogue =================
    const float v_dF = v_s[nd];
    const float u_tF = u_s[nt];
    const int   nd1  = nd + 1;

    // E1: row max (thread per row). All transport values > 0, pads -> 0.
    if (tid < 260) rhas[tid] = 0.f;
    if (tid < nt) {
        const float u = u_s[tid];
        float rmx = 0.f;
        if (F32) {
            const float* krow = Kf + (size_t)tid * ndp;
            #pragma unroll 4
            for (int c = 0; c < ndp; c += 4) {
                float4 kk = *(const float4*)(krow + c);
                float4 vv = *(const float4*)(v_s + c);
                rmx = fmaxf(rmx, tmul3(u, kk.x, vv.x));
                rmx = fmaxf(rmx, tmul3(u, kk.y, vv.y));
                rmx = fmaxf(rmx, tmul3(u, kk.z, vv.z));
                rmx = fmaxf(rmx, tmul3(u, kk.w, vv.w));
            }
        } else {
            const __half* krow = Kh + (size_t)tid * ndp;
            for (int c = 0; c < nd; c++)
                rmx = fmaxf(rmx, tmul3(u, __half2float(krow[c]), v_s[c]));
        }
        rmax_s[tid] = rmx;
    }
    __syncthreads();

    // E2: column threads — col max, then coalesced interior writes + births.
    if (tid < nd) {
        const float vc = v_s[tid];
        float cmx = 0.f;
        if (F32) {
            const float* p = Kf + tid;
            #pragma unroll 4
            for (int r = 0; r < nt; r++) { cmx = fmaxf(cmx, tmul3(u_s[r], p[0], vc)); p += ndp; }
        } else {
            const __half* p = Kh + tid;
            for (int r = 0; r < nt; r++) { cmx = fmaxf(cmx, tmul3(u_s[r], __half2float(p[0]), vc)); p += ndp; }
        }
        bool colhas = false;
        if (F32) {
            const float* p = Kf + tid;
            for (int r = 0; r < nt; r++) {
                float t = tmul3(u_s[r], p[0], vc);
                bool  a = (t == rmax_s[r]) && (t == cmx);
                size_t idx = (size_t)r * nd1 + tid;
                oT[idx] = t; oA[idx] = a ? 1.f : 0.f;
                if (a) { colhas = true; rhas[r] = 1.f; }   // benign race, all write 1
                p += ndp;
            }
        } else {
            const __half* p = Kh + tid;
            for (int r = 0; r < nt; r++) {
                float t = tmul3(u_s[r], __half2float(p[0]), vc);
                bool  a = (t == rmax_s[r]) && (t == cmx);
                size_t idx = (size_t)r * nd1 + tid;
                oT[idx] = t; oA[idx] = a ? 1.f : 0.f;
                if (a) { colhas = true; rhas[r] = 1.f; }
                p += ndp;
            }
        }
        size_t bidx = (size_t)nt * nd1 + tid;           // births row
        oT[bidx] = __fmul_rn(u_tF, vc);
        oA[bidx] = colhas ? 0.f : 1.f;
    }
    __syncthreads();

    if (tid < nt) {                                      // deaths column
        size_t idx = (size_t)tid * nd1 + nd;
        oT[idx] = __fmul_rn(u_s[tid], v_dF);
        oA[idx] = (rhas[tid] > 0.f) ? 0.f : 1.f;
    }
    if (tid == 0) {                                      // corner
        size_t idx = (size_t)nt * nd1 + nd;
        oT[idx] = __fmul_rn(u_tF, v_dF);
        oA[idx] = 0.f;
    }
    const int length = (nt + 1) * nd1;                   // zero pad tail
    for (int k = length + tid; k < L_PAD; k += NTHREADS) { oT[k] = 0.f; oA[k] = 0.f; }
}

__global__ void __launch_bounds__(NTHREADS, 1)
assoc_kernel(const float* __restrict__ aff, const int* __restrict__ ndet,
             const int* __restrict__ ntrk, float* __restrict__ outT,
             float* __restrict__ outA, int Bn)
{
    extern __shared__ float sm[];
    const int tid = threadIdx.x;

    // ---- LPT remap: block bid handles the example with cost-rank bid ----
    // cost = (nt+1)*(nd+1); descending order; ties broken by example index.
    // Deterministic, same every launch; scheduling-only change.
    int* cost_s = (int*)(sm + RMAX_OFF);    // [Bn] (Bn <= 512)
    int* pick_s = (int*)(sm + PICK_OFF);    // [1]
    if (tid < Bn) cost_s[tid] = (ntrk[tid] + 1) * (ndet[tid] + 1);
    __syncthreads();
    if (tid < Bn) {
        const int myc = cost_s[tid];
        int rank = 0;
        for (int j = 0; j < Bn; j++) {
            int cj = cost_s[j];
            rank += (cj > myc) || (cj == myc && j < tid);
        }
        if (rank == (int)blockIdx.x) *pick_s = tid;
    }
    __syncthreads();
    const int b = *pick_s;
    __syncthreads();   // everyone has read b before sm is reused

    const int nd = ndet[b];
    const int nt = ntrk[b];
    const float* affb = aff + (size_t)b * (256 * 256);
    float* oT = outT + (size_t)b * L_PAD;
    float* oA = outA + (size_t)b * L_PAD;

    int ndp4 = (nd + 3) & ~3;
    if (((ndp4 >> 2) & 1) == 0) ndp4 += 4;
    if (nt * ndp4 <= KCAP) run_ex<true >(affb, nt, nd, oT, oA, sm);
    else                   run_ex<false>(affb, nt, nd, oT, oA, sm);
}

extern "C" void kernel_launch(void* const* d_in, const int* in_sizes, int n_in,
                              void* d_out, int out_size)
{
    const float* aff  = (const float*)d_in[0];
    const int*   ndet = (const int*)d_in[1];
    const int*   ntrk = (const int*)d_in[2];
    const int    Bn   = in_sizes[1];

    float* out  = (float*)d_out;
    float* outA = out + (size_t)(out_size / 2);   // [t_flat | a_flat]

    cudaFuncSetAttribute(assoc_kernel, cudaFuncAttributeMaxDynamicSharedMemorySize, SMEM_BYTES);
    assoc_kernel<<<Bn, NTHREADS, SMEM_BYTES>>>(aff, ndet, ntrk, out, outA, Bn);
}

// round 8
// speedup vs baseline: 1.9313x; 1.0347x over previous
#include <cuda_runtime.h>
#include <cuda_fp16.h>

// B=256, T_MAX=D_MAX=256, TP=DP=257
#define NTHREADS 512
#define L_PAD    66049          // 257*257
#define EPS_C    1e-12f

// Shared layout (floats)
#define U_OFF    0              // u[260]
#define V_OFF    260            // v[260]
#define RMAX_OFF 520            // row max [260]     (reused as cost[] during remap)
#define RHAS_OFF 780            // row-has-assignment flags [260]
#define CMAX_OFF 1040           // col max [260]
#define SUP_OFF  1300           // per-warp sum(u) partials [16]
#define SVP_OFF  1316           // per-warp sum(v) partials [16]
#define SCR_OFF  1332           // half-split combine scratch [256]
#define PICK_OFF 1588           // chosen example index [1]
#define K_OFF    1592
#define SMEM_FLOATS 58112       // 232448 B / 4
#define KCAP     (SMEM_FLOATS - K_OFF)   // 56520 fp32 slots
#define SMEM_BYTES (SMEM_FLOATS * 4)

// Deterministic 3-way product: bit-identical across all transport recomputes.
__device__ __forceinline__ float tmul3(float u, float k, float v) {
    return __fmul_rn(__fmul_rn(u, k), v);
}

template<bool F32>
__device__ void run_ex(const float* __restrict__ aff, int nt, int nd,
                       float* __restrict__ oT, float* __restrict__ oA,
                       float* sm)
{
    const int tid  = threadIdx.x;
    const int lane = tid & 31;
    const int w    = tid >> 5;

    // Row pitch: odd multiple of 4 (fp32) / 8 (fp16) -> conflict-free rows.
    int ndp;
    if (F32) { ndp = (nd + 3) & ~3; if (((ndp >> 2) & 1) == 0) ndp += 4; }
    else     { ndp = (nd + 7) & ~7; if (((ndp >> 3) & 1) == 0) ndp += 8; }

    // Contiguous half-split boundaries (keep vector alignment).
    const int ndh = F32 ? ((ndp >> 1) & ~3) : ((ndp >> 1) & ~7);
    const int nth = (nt >> 1) & ~3;

    float*  u_s    = sm + U_OFF;
    float*  v_s    = sm + V_OFF;
    float*  rmax_s = sm + RMAX_OFF;
    float*  rhas   = sm + RHAS_OFF;
    float*  cmax_s = sm + CMAX_OFF;
    float*  sup    = sm + SUP_OFF;
    float*  svp    = sm + SVP_OFF;
    float*  scr    = sm + SCR_OFF;
    float*  Kf     = sm + K_OFF;
    __half* Kh     = (__half*)(sm + K_OFF);

    // Split identities: thread t and t+256 share row/col (t&255), each takes
    // one contiguous half of the reduction range.
    const int  row   = tid & 255;
    const bool up    = tid >= 256;
    const bool rowok = row < nt;
    const int  p1beg = up ? ndh : 0;
    const int  p1end = up ? ndp : ndh;
    const int  col   = row;
    const bool colok = col < nd;
    const int  p2beg = up ? nth : 0;
    const int  p2end = up ? nt  : nth;

    // ---- Pre-zero K region (padding must be exactly 0) ----
    const int kwords = F32 ? nt * ndp : (nt * ndp) >> 1;   // floats, mult of 4
    for (int i = tid * 4; i < kwords; i += NTHREADS * 4)
        *(float4*)(Kf + i) = make_float4(0.f, 0.f, 0.f, 0.f);

    // init v0 = 1 on c<=nd; interior partial sum = nd
    for (int c = tid; c < 260; c += NTHREADS) v_s[c] = (c <= nd) ? 1.f : 0.f;
    if (tid < 16) svp[tid] = (tid == 0) ? (float)nd : 0.f;
    __syncthreads();

    // ---- Build K = exp(10*aff) on interior ----
    {
        const int cq0 = F32 ? 4 * lane : 8 * lane;
        const int cq1 = 4 * lane + 128;
        for (int r = w; r < nt; r += 16) {
            const float* arow = aff + (size_t)r * 256;
            if (F32) {
                float* krow = Kf + (size_t)r * ndp;
                if (cq0 < nd) {
                    float x[4];
                    #pragma unroll
                    for (int i = 0; i < 4; i++) { int c = cq0 + i; x[i] = (c < nd) ? __expf(10.0f * arow[c]) : 0.f; }
                    *(float4*)(krow + cq0) = make_float4(x[0], x[1], x[2], x[3]);
                }
                if (cq1 < nd) {
                    float x[4];
                    #pragma unroll
                    for (int i = 0; i < 4; i++) { int c = cq1 + i; x[i] = (c < nd) ? __expf(10.0f * arow[c]) : 0.f; }
                    *(float4*)(krow + cq1) = make_float4(x[0], x[1], x[2], x[3]);
                }
            } else {
                __half* krow = Kh + (size_t)r * ndp;
                if (cq0 < nd) {
                    __half h[8];
                    #pragma unroll
                    for (int i = 0; i < 8; i++) { int c = cq0 + i; h[i] = __float2half_rn((c < nd) ? __expf(10.0f * arow[c]) : 0.f); }
                    *(uint4*)(krow + cq0) = *(uint4*)h;
                }
            }
        }
    }
    __syncthreads();

    const float ndf = (float)nd, ntf = (float)nt;
    const int   ndpS = ndp, ndp2 = 2 * ndp, ndp3 = 3 * ndp, ndp4s = 4 * ndp;
    float u_top = 0.f;

    // ================= 100 Sinkhorn iterations, half-split =================
    for (int it = 0; it < 100; ++it) {
        // ---- Pass 1: u_r = 1/((Kv)_r + v[nd] + eps) ----
        float sumv = v_s[nd];
        #pragma unroll
        for (int k = 0; k < 16; k++) sumv += svp[k];
        u_top = ndf / (sumv + EPS_C);
        const float v_dum = v_s[nd];

        float dot = 0.f;
        if (rowok) {
            float a0 = 0.f, a1 = 0.f, a2 = 0.f, a3 = 0.f;
            if (F32) {
                const float* krow = Kf + (size_t)row * ndp;
                #pragma unroll 4
                for (int c = p1beg; c < p1end; c += 4) {
                    float4 kk = *(const float4*)(krow + c);
                    float4 vv = *(const float4*)(v_s + c);     // warp-uniform broadcast
                    a0 = fmaf(kk.x, vv.x, a0); a1 = fmaf(kk.y, vv.y, a1);
                    a2 = fmaf(kk.z, vv.z, a2); a3 = fmaf(kk.w, vv.w, a3);
                }
            } else {
                const __half* krow = Kh + (size_t)row * ndp;
                #pragma unroll 2
                for (int c = p1beg; c < p1end; c += 8) {
                    uint4  raw = *(const uint4*)(krow + c);
                    float4 v0  = *(const float4*)(v_s + c);
                    float4 v1  = *(const float4*)(v_s + c + 4);
                    float2 f;
                    f = __half22float2(*(__half2*)&raw.x); a0 = fmaf(f.x, v0.x, a0); a1 = fmaf(f.y, v0.y, a1);
                    f = __half22float2(*(__half2*)&raw.y); a2 = fmaf(f.x, v0.z, a2); a3 = fmaf(f.y, v0.w, a3);
                    f = __half22float2(*(__half2*)&raw.z); a0 = fmaf(f.x, v1.x, a0); a1 = fmaf(f.y, v1.y, a1);
                    f = __half22float2(*(__half2*)&raw.w); a2 = fmaf(f.x, v1.z, a2); a3 = fmaf(f.y, v1.w, a3);
                }
            }
            dot = (a0 + a1) + (a2 + a3);
        }
        if (up && rowok) scr[row] = dot;
        __syncthreads();                                   // B1

        float u_val = 0.f;
        if (!up && rowok) {
            float d = dot + scr[row];
            u_val = 1.0f / (d + v_dum + EPS_C);
            u_s[row] = u_val;
        }
        if (tid == 0) u_s[nt] = u_top;
        float su = u_val;                                  // 0 for upper half
        #pragma unroll
        for (int o = 16; o > 0; o >>= 1) su += __shfl_xor_sync(0xffffffffu, su, o);
        if (lane == 0) sup[w] = su;
        __syncthreads();                                   // B2

        // ---- Pass 2: v_c = 1/((K^T u)_c + u_top + eps) ----
        float sumu = u_top;
        #pragma unroll
        for (int k = 0; k < 16; k++) sumu += sup[k];
        const float v_dnew = ntf / (sumu + EPS_C);

        float z = 0.f;
        if (colok) {
            float z0 = 0.f, z1 = 0.f, z2 = 0.f, z3 = 0.f;
            int r = p2beg;
            if (F32) {
                const float* p = Kf + col + (size_t)p2beg * ndp;
                for (; r + 3 < p2end; r += 4) {
                    float4 uu = *(const float4*)(u_s + r);     // broadcast (r mult of 4)
                    z0 = fmaf(p[0],     uu.x, z0);
                    z1 = fmaf(p[ndpS],  uu.y, z1);
                    z2 = fmaf(p[ndp2],  uu.z, z2);
                    z3 = fmaf(p[ndp3],  uu.w, z3);
                    p += ndp4s;
                }
                for (; r < p2end; r++) { z0 = fmaf(p[0], u_s[r], z0); p += ndpS; }
            } else {
                const __half* p = Kh + col + (size_t)p2beg * ndp;
                for (; r + 3 < p2end; r += 4) {
                    float4 uu = *(const float4*)(u_s + r);
                    z0 = fmaf(__half2float(p[0]),    uu.x, z0);
                    z1 = fmaf(__half2float(p[ndpS]), uu.y, z1);
                    z2 = fmaf(__half2float(p[ndp2]), uu.z, z2);
                    z3 = fmaf(__half2float(p[ndp3]), uu.w, z3);
                    p += ndp4s;
                }
                for (; r < p2end; r++) { z0 = fmaf(__half2float(p[0]), u_s[r], z0); p += ndpS; }
            }
            z = (z0 + z1) + (z2 + z3);
        }
        if (up && colok) scr[col] = z;
        __syncthreads();                                   // B3

        float myv = 0.f;
        if (!up && colok) {
            float zz = (z + scr[col]) + u_top;
            myv = 1.0f / (zz + EPS_C);
            v_s[col] = myv;
        }
        if (tid == 0) v_s[nd] = v_dnew;
        float sv = myv;
        #pragma unroll
        for (int o = 16; o > 0; o >>= 1) sv += __shfl_xor_sync(0xffffffffu, sv, o);
        if (lane == 0) svp[w] = sv;
        __syncthreads();                                   // B4
    }

    // ================= Epilogue (half-split sweeps) =================
    const float v_dF = v_s[nd];
    const float u_tF = u_s[nt];
    const int   nd1  = nd + 1;

    if (tid < 260) rhas[tid] = 0.f;

    // E1: row max
    float rmx = 0.f;
    if (rowok) {
        const float u = u_s[row];
        if (F32) {
            const float* krow = Kf + (size_t)row * ndp;
            #pragma unroll 4
            for (int c = p1beg; c < p1end; c += 4) {
                float4 kk = *(const float4*)(krow + c);
                float4 vv = *(const float4*)(v_s + c);
                rmx = fmaxf(rmx, tmul3(u, kk.x, vv.x));
                rmx = fmaxf(rmx, tmul3(u, kk.y, vv.y));
                rmx = fmaxf(rmx, tmul3(u, kk.z, vv.z));
                rmx = fmaxf(rmx, tmul3(u, kk.w, vv.w));
            }
        } else {
            const __half* krow = Kh + (size_t)row * ndp;
            for (int c = p1beg; c < p1end; c++)
                rmx = fmaxf(rmx, tmul3(u, __half2float(krow[c]), v_s[c]));
        }
    }
    if (up && rowok) scr[row] = rmx;
    __syncthreads();
    if (!up && rowok) rmax_s[row] = fmaxf(rmx, scr[row]);
    __syncthreads();

    // E2a: col max
    float cmx = 0.f;
    if (colok) {
        const float vc = v_s[col];
        if (F32) {
            const float* p = Kf + col + (size_t)p2beg * ndp;
            for (int r = p2beg; r < p2end; r++) { cmx = fmaxf(cmx, tmul3(u_s[r], p[0], vc)); p += ndpS; }
        } else {
            const __half* p = Kh + col + (size_t)p2beg * ndp;
            for (int r = p2beg; r < p2end; r++) { cmx = fmaxf(cmx, tmul3(u_s[r], __half2float(p[0]), vc)); p += ndpS; }
        }
    }
    if (up && colok) scr[col] = cmx;
    __syncthreads();
    if (!up && colok) cmax_s[col] = fmaxf(cmx, scr[col]);
    __syncthreads();

    // E2b: write pass over each group's row range (disjoint rows)
    float colhas = 0.f;
    if (colok) {
        const float vc = v_s[col];
        const float cf = cmax_s[col];
        if (F32) {
            const float* p = Kf + col + (size_t)p2beg * ndp;
            for (int r = p2beg; r < p2end; r++) {
                float t = tmul3(u_s[r], p[0], vc);
                bool  a = (t == rmax_s[r]) && (t == cf);
                size_t idx = (size_t)r * nd1 + col;
                oT[idx] = t; oA[idx] = a ? 1.f : 0.f;
                if (a) { colhas = 1.f; rhas[r] = 1.f; }    // benign same-value races
                p += ndpS;
            }
        } else {
            const __half* p = Kh + col + (size_t)p2beg * ndp;
            for (int r = p2beg; r < p2end; r++) {
                float t = tmul3(u_s[r], __half2float(p[0]), vc);
                bool  a = (t == rmax_s[r]) && (t == cf);
                size_t idx = (size_t)r * nd1 + col;
                oT[idx] = t; oA[idx] = a ? 1.f : 0.f;
                if (a) { colhas = 1.f; rhas[r] = 1.f; }
                p += ndpS;
            }
        }
    }
    if (up && colok) scr[col] = colhas;
    __syncthreads();
    if (!up && colok) {                                  // births row
        colhas = fmaxf(colhas, scr[col]);
        size_t bidx = (size_t)nt * nd1 + col;
        oT[bidx] = __fmul_rn(u_tF, v_s[col]);
        oA[bidx] = (colhas > 0.f) ? 0.f : 1.f;
    }
    __syncthreads();

    if (tid < nt) {                                      // deaths column
        size_t idx = (size_t)tid * nd1 + nd;
        oT[idx] = __fmul_rn(u_s[tid], v_dF);
        oA[idx] = (rhas[tid] > 0.f) ? 0.f : 1.f;
    }
    if (tid == 0) {                                      // corner
        size_t idx = (size_t)nt * nd1 + nd;
        oT[idx] = __fmul_rn(u_tF, v_dF);
        oA[idx] = 0.f;
    }
    const int length = (nt + 1) * nd1;                   // zero pad tail
    for (int k = length + tid; k < L_PAD; k += NTHREADS) { oT[k] = 0.f; oA[k] = 0.f; }
}

__global__ void __launch_bounds__(NTHREADS, 1)
assoc_kernel(const float* __restrict__ aff, const int* __restrict__ ndet,
             const int* __restrict__ ntrk, float* __restrict__ outT,
             float* __restrict__ outA, int Bn)
{
    extern __shared__ float sm[];
    const int tid = threadIdx.x;

    // ---- LPT remap: block bid handles the example with cost-rank bid ----
    int* cost_s = (int*)(sm + RMAX_OFF);    // [Bn] (Bn <= 512)
    int* pick_s = (int*)(sm + PICK_OFF);    // [1]
    if (tid < Bn) cost_s[tid] = (ntrk[tid] + 1) * (ndet[tid] + 1);
    __syncthreads();
    if (tid < Bn) {
        const int myc = cost_s[tid];
        int rank = 0;
        for (int j = 0; j < Bn; j++) {
            int cj = cost_s[j];
            rank += (cj > myc) || (cj == myc && j < tid);
        }
        if (rank == (int)blockIdx.x) *pick_s = tid;
    }
    __syncthreads();
    const int b = *pick_s;
    __syncthreads();   // everyone has read b before sm is reused

    const int nd = ndet[b];
    const int nt = ntrk[b];
    const float* affb = aff + (size_t)b * (256 * 256);
    float* oT = outT + (size_t)b * L_PAD;
    float* oA = outA + (size_t)b * L_PAD;

    int ndp4 = (nd + 3) & ~3;
    if (((ndp4 >> 2) & 1) == 0) ndp4 += 4;
    if (nt * ndp4 <= KCAP) run_ex<true >(affb, nt, nd, oT, oA, sm);
    else                   run_ex<false>(affb, nt, nd, oT, oA, sm);
}

extern "C" void kernel_launch(void* const* d_in, const int* in_sizes, int n_in,
                              void* d_out, int out_size)
{
    const float* aff  = (const float*)d_in[0];
    const int*   ndet = (const int*)d_in[1];
    const int*   ntrk = (const int*)d_in[2];
    const int    Bn   = in_sizes[1];

    float* out  = (float*)d_out;
    float* outA = out + (size_t)(out_size / 2);   // [t_flat | a_flat]

    cudaFuncSetAttribute(assoc_kernel, cudaFuncAttributeMaxDynamicSharedMemorySize, SMEM_BYTES);
    assoc_kernel<<<Bn, NTHREADS, SMEM_BYTES>>>(aff, ndet, ntrk, out, outA, Bn);
}